// round 6
// baseline (speedup 1.0000x reference)
#include <cuda_runtime.h>
#include <cstddef>

// GraphConvS: out[b,i,f] = sum_j adj[b,i,j] * (concat(sf1,sf2)[b,i,j,:] . W[:,f] + bias[f])
// Rewritten as: out[b,i,f] = (sum_j adj*x)[k] . W[k,f] + deg[b,i]*bias[f]
// Sparse gather over active j (density ~0.1), one warp per (b,i) row.

static constexpr int Bdim    = 64;
static constexpr int Mdim    = 128;
static constexpr int Fhalf   = 32;   // channels per input tensor (F1 == F2 == 32)
static constexpr int FILTERS = 32;
static constexpr int WARPS_PER_CTA = 8;
static constexpr int ROWS = Bdim * Mdim; // 8192

__global__ void __launch_bounds__(WARPS_PER_CTA * 32)
graphconvs_kernel(const float* __restrict__ sf1,
                  const float* __restrict__ sf2,
                  const float* __restrict__ adj,
                  const float* __restrict__ W,     // [64, 32] row-major (k, f)
                  const float* __restrict__ bias,  // [1, 32]
                  float* __restrict__ out)         // [B*M, 32]
{
    __shared__ float sacc[WARPS_PER_CTA][64];

    const int warp = threadIdx.x >> 5;
    const int lane = threadIdx.x & 31;
    const int row  = blockIdx.x * WARPS_PER_CTA + warp;   // b*M + i, always < 8192

    // ---- load adjacency row (128 floats, 4 per lane) ----
    const float* adj_row = adj + (size_t)row * Mdim;
    float a0 = adj_row[lane];
    float a1 = adj_row[lane + 32];
    float a2 = adj_row[lane + 64];
    float a3 = adj_row[lane + 96];

    const unsigned FULL = 0xffffffffu;
    unsigned m0 = __ballot_sync(FULL, a0 != 0.0f);
    unsigned m1 = __ballot_sync(FULL, a1 != 0.0f);
    unsigned m2 = __ballot_sync(FULL, a2 != 0.0f);
    unsigned m3 = __ballot_sync(FULL, a3 != 0.0f);

    // degree = sum of adjacency row (for the bias term)
    float deg = (a0 + a1) + (a2 + a3);
    #pragma unroll
    for (int off = 16; off > 0; off >>= 1)
        deg += __shfl_xor_sync(FULL, deg, off);

    // ---- sparse gather: acc[k] = sum_{j active} a_j * x[j,k] ----
    const float* x1 = sf1 + (size_t)row * Mdim * Fhalf;
    const float* x2 = sf2 + (size_t)row * Mdim * Fhalf;

    float acc1 = 0.0f;  // channel = lane        (from sf1)
    float acc2 = 0.0f;  // channel = lane + 32   (from sf2)

    unsigned masks[4] = {m0, m1, m2, m3};
    float    avals[4] = {a0, a1, a2, a3};

    #pragma unroll
    for (int g = 0; g < 4; ++g) {
        unsigned m = masks[g];
        const float aval = avals[g];
        while (m) {
            const int jb = __ffs(m) - 1;   // warp-uniform (mask is uniform)
            m &= m - 1u;
            const int j = g * 32 + jb;
            const float a = __shfl_sync(FULL, aval, jb);
            // two coalesced 128B line loads per active neighbor
            acc1 = fmaf(a, __ldg(&x1[j * Fhalf + lane]), acc1);
            acc2 = fmaf(a, __ldg(&x2[j * Fhalf + lane]), acc2);
        }
    }

    // ---- epilogue: tiny GEMV acc[64] . W[64,32] + deg * bias ----
    sacc[warp][lane]      = acc1;
    sacc[warp][lane + 32] = acc2;
    __syncwarp();

    float r = deg * bias[lane];
    #pragma unroll
    for (int k = 0; k < 64; ++k)
        r = fmaf(sacc[warp][k], W[k * FILTERS + lane], r);

    out[(size_t)row * FILTERS + lane] = r;
}

extern "C" void kernel_launch(void* const* d_in, const int* in_sizes, int n_in,
                              void* d_out, int out_size)
{
    // metadata order: scalar_features_1, scalar_features_2, adjacency, W, b
    const float* sf1  = (const float*)d_in[0];
    const float* sf2  = (const float*)d_in[1];
    const float* adj  = (const float*)d_in[2];
    const float* W    = (const float*)d_in[3];
    const float* bias = (const float*)d_in[4];
    float* out = (float*)d_out;

    const int blocks = ROWS / WARPS_PER_CTA;  // 1024
    graphconvs_kernel<<<blocks, WARPS_PER_CTA * 32>>>(sf1, sf2, adj, W, bias, out);
}

// round 8
// speedup vs baseline: 1.1629x; 1.1629x over previous
#include <cuda_runtime.h>
#include <cstddef>

// GraphConvS: out[b,i,f] = sum_j adj[b,i,j] * (concat(sf1,sf2)[b,i,j,:] . W[:,f] + bias[f])
//           = (sum_{j: adj=1} x[b,i,j,:]) . W + deg[b,i] * bias      (adjacency is binary)
//
// One warp per (b,i) row. Warp split into 4 neighbor-slots x 8 lanes;
// each lane loads float4 (8 lanes * 16B = one full 128B feature row),
// so one loop iteration gathers 4 active neighbors from sf1 AND sf2
// with two LDG.128 per lane.

static constexpr int Bdim    = 64;
static constexpr int Mdim    = 128;
static constexpr int Fhalf   = 32;
static constexpr int FILTERS = 32;
static constexpr int WARPS_PER_CTA = 8;
static constexpr int ROWS = Bdim * Mdim; // 8192

__global__ void __launch_bounds__(WARPS_PER_CTA * 32)
graphconvs_kernel(const float* __restrict__ sf1,
                  const float* __restrict__ sf2,
                  const float* __restrict__ adj,
                  const float* __restrict__ W,     // [64, 32] row-major (k, f)
                  const float* __restrict__ bias,  // [32]
                  float* __restrict__ out)         // [B*M, 32]
{
    __shared__ float sacc[WARPS_PER_CTA][64];

    const int warp = threadIdx.x >> 5;
    const int lane = threadIdx.x & 31;
    const int row  = blockIdx.x * WARPS_PER_CTA + warp;   // b*M + i  (< 8192)

    // ---- adjacency row -> two 64-bit active masks (bit b of M0 <-> j=b, M1 <-> j=64+b) ----
    const float* adj_row = adj + (size_t)row * Mdim;
    const float a0 = adj_row[lane];
    const float a1 = adj_row[lane + 32];
    const float a2 = adj_row[lane + 64];
    const float a3 = adj_row[lane + 96];

    const unsigned FULL = 0xffffffffu;
    unsigned long long M0 = (unsigned long long)__ballot_sync(FULL, a0 != 0.0f)
                          | ((unsigned long long)__ballot_sync(FULL, a1 != 0.0f) << 32);
    unsigned long long M1 = (unsigned long long)__ballot_sync(FULL, a2 != 0.0f)
                          | ((unsigned long long)__ballot_sync(FULL, a3 != 0.0f) << 32);

    const float deg = (float)(__popcll(M0) + __popcll(M1));  // adjacency is binary

    // ---- sparse gather: 4 neighbors per iteration, float4 per lane ----
    const float4* x1 = (const float4*)(sf1 + (size_t)row * Mdim * Fhalf);
    const float4* x2 = (const float4*)(sf2 + (size_t)row * Mdim * Fhalf);
    // neighbor j occupies float4 indices [j*8, j*8+8)

    const int g  = lane >> 3;   // neighbor slot 0..3
    const int cq = lane & 7;    // channel quad 0..7

    float4 acc1 = make_float4(0.f, 0.f, 0.f, 0.f);
    float4 acc2 = make_float4(0.f, 0.f, 0.f, 0.f);

    #pragma unroll
    for (int half = 0; half < 2; ++half) {
        unsigned long long M = half ? M1 : M0;
        const int jbase = half * 64;
        while (M) {  // warp-uniform
            // extract up to 4 set bits (ffsll(0)-1 == -1 marks an empty slot)
            int j0 = __ffsll((long long)M) - 1; M &= M - 1ULL;
            int j1 = __ffsll((long long)M) - 1; M &= M - 1ULL;
            int j2 = __ffsll((long long)M) - 1; M &= M - 1ULL;
            int j3 = __ffsll((long long)M) - 1; M &= M - 1ULL;
            const int jg = (g == 0) ? j0 : (g == 1) ? j1 : (g == 2) ? j2 : j3;
            if (jg >= 0) {
                const int idx = (jbase + jg) * 8 + cq;
                const float4 v1 = __ldg(&x1[idx]);
                const float4 v2 = __ldg(&x2[idx]);
                acc1.x += v1.x; acc1.y += v1.y; acc1.z += v1.z; acc1.w += v1.w;
                acc2.x += v2.x; acc2.y += v2.y; acc2.z += v2.z; acc2.w += v2.w;
            }
        }
    }

    // ---- merge the 4 neighbor-slot partials (xor 8, 16) ----
    #pragma unroll
    for (int off = 8; off <= 16; off <<= 1) {
        acc1.x += __shfl_xor_sync(FULL, acc1.x, off);
        acc1.y += __shfl_xor_sync(FULL, acc1.y, off);
        acc1.z += __shfl_xor_sync(FULL, acc1.z, off);
        acc1.w += __shfl_xor_sync(FULL, acc1.w, off);
        acc2.x += __shfl_xor_sync(FULL, acc2.x, off);
        acc2.y += __shfl_xor_sync(FULL, acc2.y, off);
        acc2.z += __shfl_xor_sync(FULL, acc2.z, off);
        acc2.w += __shfl_xor_sync(FULL, acc2.w, off);
    }
    if (lane < 8) {
        ((float4*)&sacc[warp][0])[lane]  = acc1;   // channels k = lane*4..+3
        ((float4*)&sacc[warp][32])[lane] = acc2;   // channels k = 32+lane*4..+3
    }
    __syncwarp();

    // ---- epilogue GEMV: r[f] = deg*bias[f] + sum_k acc[k]*W[k,f] ----
    float r = deg * bias[lane];
    #pragma unroll
    for (int k = 0; k < 64; ++k)
        r = fmaf(sacc[warp][k], W[k * FILTERS + lane], r);

    out[(size_t)row * FILTERS + lane] = r;
}

extern "C" void kernel_launch(void* const* d_in, const int* in_sizes, int n_in,
                              void* d_out, int out_size)
{
    // metadata order: scalar_features_1, scalar_features_2, adjacency, W, b
    const float* sf1  = (const float*)d_in[0];
    const float* sf2  = (const float*)d_in[1];
    const float* adj  = (const float*)d_in[2];
    const float* W    = (const float*)d_in[3];
    const float* bias = (const float*)d_in[4];
    float* out = (float*)d_out;

    graphconvs_kernel<<<ROWS / WARPS_PER_CTA, WARPS_PER_CTA * 32>>>(
        sf1, sf2, adj, W, bias, out);
}

// round 9
// speedup vs baseline: 1.3851x; 1.1910x over previous
#include <cuda_runtime.h>
#include <cstddef>

// GraphConvS: out[b,i,f] = sum_j adj[b,i,j] * (concat(sf1,sf2)[b,i,j,:] . W[:,f] + bias[f])
//           = (sum_{j: adj=1} x[b,i,j,:]) . W + deg[b,i] * bias      (adjacency is binary)
//
// One warp per (b,i) row. Active-neighbor indices are compacted into a
// per-warp shared list via ballot+popc prefix ranks (no serial bit-scan),
// then gathered with a dependence-free unrolled loop: warp = 4 neighbor
// slots x 8 lanes, each lane one float4 (8 lanes * 16B = full 128B row).
// Epilogue uses W transposed in shared (float4, conflict-free) with split
// FMA accumulators.

static constexpr int Bdim    = 64;
static constexpr int Mdim    = 128;
static constexpr int Fhalf   = 32;
static constexpr int FILTERS = 32;
static constexpr int WARPS_PER_CTA = 8;
static constexpr int ROWS = Bdim * Mdim; // 8192
static constexpr int WT_STRIDE = 68;     // 68 % 32 == 4 -> LDS.128 phase-conflict-free

__global__ void __launch_bounds__(WARPS_PER_CTA * 32)
graphconvs_kernel(const float* __restrict__ sf1,
                  const float* __restrict__ sf2,
                  const float* __restrict__ adj,
                  const float* __restrict__ W,     // [64, 32] row-major (k, f)
                  const float* __restrict__ bias,  // [32]
                  float* __restrict__ out)         // [B*M, 32]
{
    __shared__ float         WTs[FILTERS][WT_STRIDE];     // WT[f][k] = W[k][f]
    __shared__ float         sacc[WARPS_PER_CTA][64];
    __shared__ unsigned char jl[WARPS_PER_CTA][Mdim];     // compacted neighbor ids

    const int tid  = threadIdx.x;
    const int warp = tid >> 5;
    const int lane = tid & 31;
    const int row  = blockIdx.x * WARPS_PER_CTA + warp;   // b*M + i  (< 8192)

    // ---- stage W transposed into shared (2048 coalesced loads per CTA) ----
    #pragma unroll
    for (int idx = tid; idx < 64 * FILTERS; idx += WARPS_PER_CTA * 32) {
        const int k = idx >> 5, f = idx & 31;
        WTs[f][k] = W[idx];
    }
    // (ordering vs. reads enforced by the __syncthreads before the epilogue)

    // ---- adjacency row: one LDG.128 per lane; compact active j's via ranks ----
    const float4 av = __ldg((const float4*)(adj + (size_t)row * Mdim) + lane);

    const unsigned FULL = 0xffffffffu;
    const unsigned b0 = __ballot_sync(FULL, av.x != 0.0f);
    const unsigned b1 = __ballot_sync(FULL, av.y != 0.0f);
    const unsigned b2 = __ballot_sync(FULL, av.z != 0.0f);
    const unsigned b3 = __ballot_sync(FULL, av.w != 0.0f);

    const unsigned lt = (1u << lane) - 1u;
    const int c0 = __popc(b0);
    const int c1 = c0 + __popc(b1);
    const int c2 = c1 + __popc(b2);
    const int total = c2 + __popc(b3);

    unsigned char* jlw = jl[warp];
    if (av.x != 0.0f) jlw[     __popc(b0 & lt)] = (unsigned char)(4 * lane + 0);
    if (av.y != 0.0f) jlw[c0 + __popc(b1 & lt)] = (unsigned char)(4 * lane + 1);
    if (av.z != 0.0f) jlw[c1 + __popc(b2 & lt)] = (unsigned char)(4 * lane + 2);
    if (av.w != 0.0f) jlw[c2 + __popc(b3 & lt)] = (unsigned char)(4 * lane + 3);
    __syncwarp();

    const float deg = (float)total;   // adjacency is binary

    // ---- gather: slot g takes list entries t = g, g+4, ... (order-free sum) ----
    const float4* x1 = (const float4*)(sf1 + (size_t)row * Mdim * Fhalf);
    const float4* x2 = (const float4*)(sf2 + (size_t)row * Mdim * Fhalf);
    const int g  = lane >> 3;   // neighbor slot 0..3
    const int cq = lane & 7;    // channel quad 0..7

    float4 acc1 = make_float4(0.f, 0.f, 0.f, 0.f);
    float4 acc2 = make_float4(0.f, 0.f, 0.f, 0.f);

    #pragma unroll 4
    for (int t = g; t < total; t += 4) {
        const int idx = (int)jlw[t] * 8 + cq;
        const float4 v1 = __ldg(&x1[idx]);
        const float4 v2 = __ldg(&x2[idx]);
        acc1.x += v1.x; acc1.y += v1.y; acc1.z += v1.z; acc1.w += v1.w;
        acc2.x += v2.x; acc2.y += v2.y; acc2.z += v2.z; acc2.w += v2.w;
    }

    // ---- merge the 4 neighbor-slot partials (xor 8, 16) ----
    #pragma unroll
    for (int off = 8; off <= 16; off <<= 1) {
        acc1.x += __shfl_xor_sync(FULL, acc1.x, off);
        acc1.y += __shfl_xor_sync(FULL, acc1.y, off);
        acc1.z += __shfl_xor_sync(FULL, acc1.z, off);
        acc1.w += __shfl_xor_sync(FULL, acc1.w, off);
        acc2.x += __shfl_xor_sync(FULL, acc2.x, off);
        acc2.y += __shfl_xor_sync(FULL, acc2.y, off);
        acc2.z += __shfl_xor_sync(FULL, acc2.z, off);
        acc2.w += __shfl_xor_sync(FULL, acc2.w, off);
    }
    if (lane < 8) {
        ((float4*)&sacc[warp][0])[lane]  = acc1;   // channels k = lane*4..+3
        ((float4*)&sacc[warp][32])[lane] = acc2;   // channels k = 32+lane*4..+3
    }
    __syncthreads();   // orders WTs writes (and sacc, per-warp) before reads

    // ---- epilogue GEMV: r[f] = deg*bias[f] + sum_k acc[k]*WT[f][k] ----
    float p0 = 0.f, p1 = 0.f;
    #pragma unroll
    for (int k4 = 0; k4 < 16; ++k4) {
        const float4 s = *(const float4*)&sacc[warp][k4 * 4];     // broadcast
        const float4 w = *(const float4*)&WTs[lane][k4 * 4];      // conflict-free
        p0 = fmaf(s.x, w.x, p0); p1 = fmaf(s.y, w.y, p1);
        p0 = fmaf(s.z, w.z, p0); p1 = fmaf(s.w, w.w, p1);
    }
    out[(size_t)row * FILTERS + lane] = fmaf(deg, __ldg(&bias[lane]), p0 + p1);
}

extern "C" void kernel_launch(void* const* d_in, const int* in_sizes, int n_in,
                              void* d_out, int out_size)
{
    // metadata order: scalar_features_1, scalar_features_2, adjacency, W, b
    const float* sf1  = (const float*)d_in[0];
    const float* sf2  = (const float*)d_in[1];
    const float* adj  = (const float*)d_in[2];
    const float* W    = (const float*)d_in[3];
    const float* bias = (const float*)d_in[4];
    float* out = (float*)d_out;

    graphconvs_kernel<<<ROWS / WARPS_PER_CTA, WARPS_PER_CTA * 32>>>(
        sf1, sf2, adj, W, bias, out);
}